// round 9
// baseline (speedup 1.0000x reference)
#include <cuda_runtime.h>
#include <cuda_fp16.h>
#include <cuda_pipeline.h>
#include <math.h>

#define Bb 128
#define Rr 1152
#define CI 8
#define Cc 10
#define Oo 16
#define NS  (Cc*Bb*Oo)   /* 20480 */
#define RT 16
#define NRT (Rr/RT)      /* 72 */
#define NIT 1280         /* k_it CTA count (1 cb per CTA) */
#define TILE_B (Rr*Oo*2) /* 36864 bytes of u per cb */

// Static device scratch.
__device__ __half g_uh[(size_t)Cc*Bb*Rr*Oo];  // 47 MB, u in fp16
__device__ float2 g_S0[NS/2];                 // atomic accumulators for sum_r u
__device__ float  g_S[NS];                    // current s[c][b][o]
__device__ float  g_V[NS];                    // accumulated V (pre-scaled log2e)
__device__ float  g_n2a[20];                  // sum-sq partials after s1
__device__ float  g_n2b[NIT];                 // after iter-2
__device__ float  g_n2c[NIT];                 // after iter-3

// ---------------------------------------------------------------------------
// f32x2 packed helpers (Blackwell FFMA2 path — only reachable via PTX)
// ---------------------------------------------------------------------------
typedef unsigned long long ull;
__device__ __forceinline__ ull pk2(float lo, float hi) {
    ull r; asm("mov.b64 %0, {%1, %2};" : "=l"(r) : "f"(lo), "f"(hi)); return r;
}
__device__ __forceinline__ void upk2(ull v, float& lo, float& hi) {
    asm("mov.b64 {%0, %1}, %2;" : "=f"(lo), "=f"(hi) : "l"(v));
}
__device__ __forceinline__ ull fma2(ull a, ull b, ull c) {
    ull r; asm("fma.rn.f32x2 %0, %1, %2, %3;" : "=l"(r) : "l"(a), "l"(b), "l"(c)); return r;
}
__device__ __forceinline__ ull add2(ull a, ull b) {
    ull r; asm("add.rn.f32x2 %0, %1, %2;" : "=l"(r) : "l"(a), "l"(b)); return r;
}

// ---------------------------------------------------------------------------
// k_u: u[c,b,r,o] = sum_i x[b,r,i]*W[c,r,i,o] -> fp16; accumulates sum_r u
// into g_S0 via warp shuffles + atomicAdd(float2). grid (72,10) x 128 thr.
// (near FMA floor ~11us; unchanged from R8)
// ---------------------------------------------------------------------------
__global__ __launch_bounds__(128) void k_u(const float* __restrict__ x,
                                           const float* __restrict__ W)
{
    const int rt  = blockIdx.x, c = blockIdx.y;
    const int tid = threadIdx.x;
    const int o2  = tid & 7;
    const int rl  = tid >> 3;          // 0..15
    const int r   = rt * RT + rl;

    float w0[8], w1[8];
    {
        const float* Wp = W + (((size_t)c*Rr + r)*CI)*Oo + 2*o2;
        #pragma unroll
        for (int i = 0; i < 8; i++) {
            float2 v = *(const float2*)(Wp + i*Oo);
            w0[i] = v.x; w1[i] = v.y;
        }
    }

    const float4* xp = (const float4*)x;
    const size_t  xstep = (size_t)Rr*CI/4;
    const size_t  xbase = (size_t)r*CI/4;

    half2* udst = (half2*)g_uh + ((size_t)c*Bb*Rr + r)*8 + o2;

    float4 xa = xp[xbase], xb = xp[xbase+1];
    for (int b = 0; b < Bb; b++) {
        float4 na, nb;
        if (b + 1 < Bb) {
            size_t nx = xbase + (size_t)(b+1)*xstep;
            na = xp[nx]; nb = xp[nx+1];
        }
        float u0, u1;
        u0 =           xa.x*w0[0];        u1 =           xa.x*w1[0];
        u0 = fmaf(xa.y, w0[1], u0);       u1 = fmaf(xa.y, w1[1], u1);
        u0 = fmaf(xa.z, w0[2], u0);       u1 = fmaf(xa.z, w1[2], u1);
        u0 = fmaf(xa.w, w0[3], u0);       u1 = fmaf(xa.w, w1[3], u1);
        u0 = fmaf(xb.x, w0[4], u0);       u1 = fmaf(xb.x, w1[4], u1);
        u0 = fmaf(xb.y, w0[5], u0);       u1 = fmaf(xb.y, w1[5], u1);
        u0 = fmaf(xb.z, w0[6], u0);       u1 = fmaf(xb.z, w1[6], u1);
        u0 = fmaf(xb.w, w0[7], u0);       u1 = fmaf(xb.w, w1[7], u1);
        udst[(size_t)b*Rr*8] = __floats2half2_rn(u0, u1);

        float p0 = u0, p1 = u1;
        p0 += __shfl_xor_sync(0xffffffffu, p0, 8);
        p1 += __shfl_xor_sync(0xffffffffu, p1, 8);
        p0 += __shfl_xor_sync(0xffffffffu, p0, 16);
        p1 += __shfl_xor_sync(0xffffffffu, p1, 16);
        if ((tid & 31) < 8)
            atomicAdd(&g_S0[(c*Bb + b)*8 + o2], make_float2(p0, p1));

        xa = na; xb = nb;
    }
}

// ---------------------------------------------------------------------------
// k_s1: s1 = g_S0/R -> g_S; per-CTA sum s1^2 -> g_n2a[20]. grid 20 x 1024.
// ---------------------------------------------------------------------------
__global__ __launch_bounds__(1024) void k_s1()
{
    const int tid = threadIdx.x;
    const int i   = blockIdx.x*1024 + tid;
    const float s = ((const float*)g_S0)[i] * (1.0f / (float)Rr);
    g_S[i] = s;
    __shared__ float sh[1024];
    sh[tid] = s*s;
    __syncthreads();
    for (int st = 512; st > 0; st >>= 1) {
        if (tid < st) sh[tid] += sh[tid + st];
        __syncthreads();
    }
    if (tid == 0) g_n2a[blockIdx.x] = sh[0];
}

// ---------------------------------------------------------------------------
// k_it: cp.async the full 36.8KB u-tile for this cb into smem (18 LDGSTS per
// thread, zero register cost -> deep DRAM MLP), overlap with the K-prologue,
// then compute exp/sums from smem with packed f32x2. Epilogue reductions
// alias into the same smem after a barrier.
// iter3==0: V = K*s_prev (stored to g_V).  iter3==1: V = g_V + K*s_prev.
// grid (128, 10) = 1280 CTAs x 128 thr, 1 cb per CTA.
// ---------------------------------------------------------------------------
__global__ __launch_bounds__(128) void k_it(const float* __restrict__ n2part,
                                            int nn,
                                            float* __restrict__ n2out,
                                            int iter3)
{
    extern __shared__ __align__(16) char dsm[];   // TILE_B bytes
    __shared__ float shn[128];

    const int cb  = blockIdx.y*Bb + blockIdx.x;
    const int tid = threadIdx.x;
    const int p   = (tid & 1) * 8;

    // 1) issue async copy of the whole u tile (no destination registers)
    {
        const char* src = (const char*)(g_uh + (size_t)cb*Rr*Oo);
        #pragma unroll
        for (int k = 0; k < 18; k++)
            __pipeline_memcpy_async(dsm + tid*16 + k*2048,
                                    src + tid*16 + k*2048, 16);
        __pipeline_commit();
    }

    // 2) prologue (overlaps the async loads): global n2 -> K, build V
    float acc = 0.f;
    for (int i = tid; i < nn; i += 128) acc += n2part[i];
    shn[tid] = acc;
    __syncthreads();
    for (int st = 64; st > 0; st >>= 1) {
        if (tid < st) shn[tid] += shn[tid + st];
        __syncthreads();
    }
    const float n2 = shn[0];
    const float K  = (sqrtf(n2) / (1.0f + n2)) * 1.4426950408889634f;

    ull V2[4];
    #pragma unroll
    for (int j = 0; j < 4; j++) {
        const int i0 = cb*16 + p + 2*j;
        float v0 = K * g_S[i0],   v1 = K * g_S[i0+1];
        if (iter3) { v0 += g_V[i0]; v1 += g_V[i0+1]; }
        V2[j] = pk2(v0, v1);
    }
    if (!iter3 && tid < 16) g_V[cb*16 + tid] = K * g_S[cb*16 + tid];

    const ull MAGIC2  = pk2(12582912.0f, 12582912.0f);
    const ull NMAGIC2 = pk2(-12582912.0f, -12582912.0f);
    const ull CF4 = pk2(0.0096181298f, 0.0096181298f);
    const ull CF3 = pk2(0.0555041087f, 0.0555041087f);
    const ull CF2 = pk2(0.2402265070f, 0.2402265070f);
    const ull CF1 = pk2(0.6931471806f, 0.6931471806f);
    const ull CF0 = pk2(1.0f, 1.0f);
    const ull SIGN64 = 0x8000000080000000ULL;

    // 3) wait for the tile
    __pipeline_wait_prior(0);
    __syncthreads();

    // 4) compute from smem
    const float4* up = (const float4*)dsm;
    ull z2[4], s2[4];
    #pragma unroll
    for (int j = 0; j < 4; j++) { z2[j] = 0ULL; s2[j] = 0ULL; }

    #pragma unroll 6
    for (int k = 0; k < 18; k++) {
        float4 cur = up[tid + k*128];
        const half2* hp = (const half2*)&cur;
        #pragma unroll
        for (int j = 0; j < 4; j++) {
            float2 fu = __half22float2(hp[j]);
            ull u2 = pk2(fu.x, fu.y);
            ull t2 = fma2(u2, V2[j], MAGIC2);      // z + MAGIC (rounds n)
            ull g2 = add2(t2, NMAGIC2);            // n (exact)
            ull f2 = fma2(u2, V2[j], g2 ^ SIGN64); // f = z - n, single rounding
            ull p2 = fma2(CF4, f2, CF3);
            p2 = fma2(p2, f2, CF2);
            p2 = fma2(p2, f2, CF1);
            p2 = fma2(p2, f2, CF0);
            float tlo, thi, plo, phi;
            upk2(t2, tlo, thi);
            upk2(p2, plo, phi);
            float e0 = __int_as_float(__float_as_int(plo) + (__float_as_int(tlo) << 23));
            float e1 = __int_as_float(__float_as_int(phi) + (__float_as_int(thi) << 23));
            ull e2 = pk2(e0, e1);
            z2[j] = add2(z2[j], e2);
            s2[j] = fma2(e2, u2, s2[j]);
        }
    }

    float z[8], s[8];
    #pragma unroll
    for (int j = 0; j < 4; j++) {
        upk2(z2[j], z[2*j], z[2*j+1]);
        upk2(s2[j], s[2*j], s[2*j+1]);
    }

    // 5) epilogue reductions (alias into dsm; tile fully consumed)
    __syncthreads();
    float* zs  = (float*)dsm;            // 8*132
    float* ssm = zs  + 8*132;            // 8*132
    float* pAz = ssm + 8*132;            // 128
    float* pAs = pAz + 128;              // 128

    const int row = (tid >> 1) + (tid & 1)*64;
    #pragma unroll
    for (int j = 0; j < 8; j++) { zs[j*132 + row] = z[j]; ssm[j*132 + row] = s[j]; }
    __syncthreads();
    {
        const int h = tid >> 6, col = (tid >> 3) & 7, grp = tid & 7;
        float az = 0.f, as = 0.f;
        #pragma unroll
        for (int i = 0; i < 8; i++) {
            const int a = col*132 + h*64 + grp + 8*i;
            az += zs[a]; as += ssm[a];
        }
        pAz[tid] = az; pAs[tid] = as;
    }
    __syncthreads();
    float qacc = 0.f;
    if (tid < 16) {
        const int h = tid >> 3, col = tid & 7;
        float zt = 0.f, st = 0.f;
        #pragma unroll
        for (int g = 0; g < 8; g++) {
            const int a = h*64 + col*8 + g;
            zt += pAz[a]; st += pAs[a];
        }
        const float sn = st / zt;
        g_S[cb*16 + tid] = sn;
        qacc = sn * sn;
    }
    shn[tid] = qacc;
    __syncthreads();
    if (tid == 0) {
        float t = 0.f;
        #pragma unroll
        for (int i = 0; i < 16; i++) t += shn[i];
        n2out[blockIdx.y*gridDim.x + blockIdx.x] = t;
    }
}

// ---------------------------------------------------------------------------
// k_fin: out = f3 * s3. grid 20 x 1024.
// ---------------------------------------------------------------------------
__global__ __launch_bounds__(1024) void k_fin(float* __restrict__ outp)
{
    const int tid = threadIdx.x;
    __shared__ float sh[1024];
    float acc = g_n2c[tid];
    if (tid < NIT - 1024) acc += g_n2c[1024 + tid];
    sh[tid] = acc;
    __syncthreads();
    for (int st = 512; st > 0; st >>= 1) {
        if (tid < st) sh[tid] += sh[tid + st];
        __syncthreads();
    }
    const float n2 = sh[0];
    const float f  = sqrtf(n2) / (1.0f + n2);
    const int i = blockIdx.x*1024 + tid;
    outp[i] = f * g_S[i];
}

// ---------------------------------------------------------------------------
extern "C" void kernel_launch(void* const* d_in, const int* in_sizes, int n_in,
                              void* d_out, int out_size)
{
    const float* x = (const float*)d_in[0];   // [128,1152,8]
    const float* W = (const float*)d_in[1];   // [10,1152,8,16]
    float* out = (float*)d_out;               // 20480 floats
    (void)in_sizes; (void)n_in; (void)out_size;

    float *n2a, *n2b, *n2c; void* s0;
    cudaGetSymbolAddress((void**)&n2a, g_n2a);
    cudaGetSymbolAddress((void**)&n2b, g_n2b);
    cudaGetSymbolAddress((void**)&n2c, g_n2c);
    cudaGetSymbolAddress(&s0, g_S0);

    static int attr_done = 0;
    if (!attr_done) {
        cudaFuncSetAttribute(k_it, cudaFuncAttributeMaxDynamicSharedMemorySize,
                             TILE_B);
        attr_done = 1;
    }

    cudaMemsetAsync(s0, 0, NS*sizeof(float), 0);
    k_u  <<<dim3(NRT, Cc), 128>>>(x, W);
    k_s1 <<<20, 1024>>>();                                      // iter 1 + n2
    k_it <<<dim3(Bb, Cc), 128, TILE_B>>>(n2a,   20, n2b, 0);    // iter 2
    k_it <<<dim3(Bb, Cc), 128, TILE_B>>>(n2b, NIT, n2c, 1);     // iter 3
    k_fin<<<20, 1024>>>(out);                                   // final squash
}

// round 10
// speedup vs baseline: 1.1253x; 1.1253x over previous
#include <cuda_runtime.h>
#include <cuda_fp16.h>
#include <cuda_pipeline.h>
#include <math.h>

#define Bb 128
#define Rr 1152
#define CI 8
#define Cc 10
#define Oo 16
#define NS  (Cc*Bb*Oo)   /* 20480 */
#define RT 16
#define NRT (Rr/RT)      /* 72 */
#define NIT 1280         /* k_it CTA count */
#define DEPTH 6
#define CHB 2048         /* chunk bytes: 128 thr * 16B */
#define NCHUNK 18        /* 36864 / 2048 */

// Static device scratch.
__device__ __half g_uh[(size_t)Cc*Bb*Rr*Oo];  // 47 MB, u in fp16
__device__ float  g_S[NS];                    // current s[c][b][o]
__device__ float  g_V[NS];                    // accumulated V (pre-scaled log2e)
__device__ float  g_n2a[640];                 // sum-sq partials after s1
__device__ float  g_n2b[NIT];                 // after iter-2
__device__ float  g_n2c[NIT];                 // after iter-3

// ---------------------------------------------------------------------------
// f32x2 packed helpers (Blackwell FFMA2 path — only reachable via PTX)
// ---------------------------------------------------------------------------
typedef unsigned long long ull;
__device__ __forceinline__ ull pk2(float lo, float hi) {
    ull r; asm("mov.b64 %0, {%1, %2};" : "=l"(r) : "f"(lo), "f"(hi)); return r;
}
__device__ __forceinline__ void upk2(ull v, float& lo, float& hi) {
    asm("mov.b64 {%0, %1}, %2;" : "=f"(lo), "=f"(hi) : "l"(v));
}
__device__ __forceinline__ ull fma2(ull a, ull b, ull c) {
    ull r; asm("fma.rn.f32x2 %0, %1, %2, %3;" : "=l"(r) : "l"(a), "l"(b), "l"(c)); return r;
}
__device__ __forceinline__ ull add2(ull a, ull b) {
    ull r; asm("add.rn.f32x2 %0, %1, %2;" : "=l"(r) : "l"(a), "l"(b)); return r;
}

// ---------------------------------------------------------------------------
// k_u: u[c,b,r,o] = sum_i x[b,r,i]*W[c,r,i,o] -> fp16. Pure compute, no smem,
// no barriers, no atomics (R5-proven). grid (72,10) x 128 thr.
// ---------------------------------------------------------------------------
__global__ __launch_bounds__(128) void k_u(const float* __restrict__ x,
                                           const float* __restrict__ W)
{
    const int rt  = blockIdx.x, c = blockIdx.y;
    const int tid = threadIdx.x;
    const int o2  = tid & 7;
    const int rl  = tid >> 3;          // 0..15
    const int r   = rt * RT + rl;

    float w0[8], w1[8];
    {
        const float* Wp = W + (((size_t)c*Rr + r)*CI)*Oo + 2*o2;
        #pragma unroll
        for (int i = 0; i < 8; i++) {
            float2 v = *(const float2*)(Wp + i*Oo);
            w0[i] = v.x; w1[i] = v.y;
        }
    }

    const float4* xp = (const float4*)x;
    const size_t  xstep = (size_t)Rr*CI/4;
    const size_t  xbase = (size_t)r*CI/4;

    half2* udst = (half2*)g_uh + ((size_t)c*Bb*Rr + r)*8 + o2;

    float4 xa = xp[xbase], xb = xp[xbase+1];
    for (int b = 0; b < Bb; b++) {
        float4 na, nb;
        if (b + 1 < Bb) {
            size_t nx = xbase + (size_t)(b+1)*xstep;
            na = xp[nx]; nb = xp[nx+1];
        }
        float u0, u1;
        u0 =           xa.x*w0[0];        u1 =           xa.x*w1[0];
        u0 = fmaf(xa.y, w0[1], u0);       u1 = fmaf(xa.y, w1[1], u1);
        u0 = fmaf(xa.z, w0[2], u0);       u1 = fmaf(xa.z, w1[2], u1);
        u0 = fmaf(xa.w, w0[3], u0);       u1 = fmaf(xa.w, w1[3], u1);
        u0 = fmaf(xb.x, w0[4], u0);       u1 = fmaf(xb.x, w1[4], u1);
        u0 = fmaf(xb.y, w0[5], u0);       u1 = fmaf(xb.y, w1[5], u1);
        u0 = fmaf(xb.z, w0[6], u0);       u1 = fmaf(xb.z, w1[6], u1);
        u0 = fmaf(xb.w, w0[7], u0);       u1 = fmaf(xb.w, w1[7], u1);
        udst[(size_t)b*Rr*8] = __floats2half2_rn(u0, u1);
        xa = na; xb = nb;
    }
}

// ---------------------------------------------------------------------------
// k_s0: s1[cb,o] = mean_r u; per-CTA sum s1^2 -> g_n2a[640]. grid (64,10),
// 256 thr, 2 cb per CTA, 9 front-batched LDG.128 (R5-proven fast stream).
// ---------------------------------------------------------------------------
__global__ __launch_bounds__(256) void k_s0()
{
    const int bx = blockIdx.x, c = blockIdx.y;
    const int tid = threadIdx.x;
    __shared__ float ss[8*256];     // column-major: ss[j*256 + row]
    __shared__ float pA[256];
    __shared__ float shn[256];

    float qacc = 0.f;
    for (int bb = 0; bb < 2; bb++) {
        const int cb = c*Bb + bx*2 + bb;
        const float4* up = (const float4*)(g_uh + (size_t)cb*Rr*Oo);

        float s[8];
        #pragma unroll
        for (int j = 0; j < 8; j++) s[j] = 0.f;
        #pragma unroll
        for (int k = 0; k < 9; k++) {
            float4 raw = up[tid + k*256];
            const half2* hp = (const half2*)&raw;
            #pragma unroll
            for (int j = 0; j < 4; j++) {
                float2 f2 = __half22float2(hp[j]);
                s[2*j]   += f2.x;
                s[2*j+1] += f2.y;
            }
        }
        const int row = (tid >> 1) + (tid & 1)*128;
        #pragma unroll
        for (int j = 0; j < 8; j++) ss[j*256 + row] = s[j];
        __syncthreads();
        {
            const int h = tid >> 7, col = (tid >> 4) & 7, grp = tid & 15;
            float a = 0.f;
            #pragma unroll
            for (int i = 0; i < 8; i++) a += ss[col*256 + h*128 + grp + 16*i];
            pA[tid] = a;
        }
        __syncthreads();
        if (tid < 16) {
            const int h = tid >> 3, col = tid & 7;
            float st = 0.f;
            #pragma unroll
            for (int g2 = 0; g2 < 16; g2++) st += pA[h*128 + col*16 + g2];
            const float sn = st * (1.0f / (float)Rr);
            g_S[cb*16 + tid] = sn;
            qacc += sn * sn;
        }
        __syncthreads();
    }
    shn[tid] = qacc;
    __syncthreads();
    if (tid == 0) {
        float t = 0.f;
        #pragma unroll
        for (int i = 0; i < 16; i++) t += shn[i];
        g_n2a[blockIdx.y*gridDim.x + blockIdx.x] = t;
    }
}

// ---------------------------------------------------------------------------
// k_it: ring-buffered cp.async pipeline (depth 6 x 2KB), barrier-free
// mainloop (each thread consumes only the bytes it copied). Exp via packed
// f32x2. Epilogue reductions alias into the drained ring.
// iter3==0: V = K*s_prev (stored to g_V).  iter3==1: V = g_V + K*s_prev.
// grid (128, 10) = 1280 CTAs x 128 thr, 1 cb per CTA.
// ---------------------------------------------------------------------------
__global__ __launch_bounds__(128) void k_it(const float* __restrict__ n2part,
                                            int nn,
                                            float* __restrict__ n2out,
                                            int iter3)
{
    __shared__ __align__(16) char ring[DEPTH*CHB];   // 12 KB
    __shared__ float shn[128];

    const int cb  = blockIdx.y*Bb + blockIdx.x;
    const int tid = threadIdx.x;
    const int p   = (tid & 1) * 8;
    const char* src = (const char*)(g_uh + (size_t)cb*Rr*Oo);
    const int toff = tid*16;

    // prologue: issue first DEPTH chunks (one commit group per chunk)
    #pragma unroll
    for (int k = 0; k < DEPTH; k++) {
        __pipeline_memcpy_async(ring + k*CHB + toff, src + k*CHB + toff, 16);
        __pipeline_commit();
    }

    // overlap: global n2 -> K
    float acc = 0.f;
    for (int i = tid; i < nn; i += 128) acc += n2part[i];
    shn[tid] = acc;
    __syncthreads();
    for (int st = 64; st > 0; st >>= 1) {
        if (tid < st) shn[tid] += shn[tid + st];
        __syncthreads();
    }
    const float n2 = shn[0];
    const float K  = (sqrtf(n2) / (1.0f + n2)) * 1.4426950408889634f;

    ull V2[4];
    #pragma unroll
    for (int j = 0; j < 4; j++) {
        const int i0 = cb*16 + p + 2*j;
        float v0 = K * g_S[i0],   v1 = K * g_S[i0+1];
        if (iter3) { v0 += g_V[i0]; v1 += g_V[i0+1]; }
        V2[j] = pk2(v0, v1);
    }
    if (!iter3 && tid < 16) g_V[cb*16 + tid] = K * g_S[cb*16 + tid];

    const ull MAGIC2  = pk2(12582912.0f, 12582912.0f);
    const ull NMAGIC2 = pk2(-12582912.0f, -12582912.0f);
    const ull CF4 = pk2(0.0096181298f, 0.0096181298f);
    const ull CF3 = pk2(0.0555041087f, 0.0555041087f);
    const ull CF2 = pk2(0.2402265070f, 0.2402265070f);
    const ull CF1 = pk2(0.6931471806f, 0.6931471806f);
    const ull CF0 = pk2(1.0f, 1.0f);
    const ull SIGN64 = 0x8000000080000000ULL;

    ull z2[4], s2[4];
    #pragma unroll
    for (int j = 0; j < 4; j++) { z2[j] = 0ULL; s2[j] = 0ULL; }

    // barrier-free pipelined mainloop
    #pragma unroll
    for (int k = 0; k < NCHUNK; k++) {
        __pipeline_wait_prior(DEPTH - 1);            // chunk k arrived
        float4 cur = *(const float4*)(ring + (k % DEPTH)*CHB + toff);
        if (k + DEPTH < NCHUNK)
            __pipeline_memcpy_async(ring + (k % DEPTH)*CHB + toff,
                                    src + (k + DEPTH)*CHB + toff, 16);
        __pipeline_commit();                          // keep group accounting
        const half2* hp = (const half2*)&cur;
        #pragma unroll
        for (int j = 0; j < 4; j++) {
            float2 fu = __half22float2(hp[j]);
            ull u2 = pk2(fu.x, fu.y);
            ull t2 = fma2(u2, V2[j], MAGIC2);      // z + MAGIC (rounds n)
            ull g2 = add2(t2, NMAGIC2);            // n (exact)
            ull f2 = fma2(u2, V2[j], g2 ^ SIGN64); // f = z - n, single rounding
            ull p2 = fma2(CF4, f2, CF3);
            p2 = fma2(p2, f2, CF2);
            p2 = fma2(p2, f2, CF1);
            p2 = fma2(p2, f2, CF0);
            float tlo, thi, plo, phi;
            upk2(t2, tlo, thi);
            upk2(p2, plo, phi);
            float e0 = __int_as_float(__float_as_int(plo) + (__float_as_int(tlo) << 23));
            float e1 = __int_as_float(__float_as_int(phi) + (__float_as_int(thi) << 23));
            ull e2 = pk2(e0, e1);
            z2[j] = add2(z2[j], e2);
            s2[j] = fma2(e2, u2, s2[j]);
        }
    }

    float z[8], s[8];
    #pragma unroll
    for (int j = 0; j < 4; j++) {
        upk2(z2[j], z[2*j], z[2*j+1]);
        upk2(s2[j], s[2*j], s[2*j+1]);
    }

    // epilogue reductions alias into the drained ring
    __syncthreads();
    float* zs  = (float*)ring;           // 8*132 = 4224 B
    float* ssm = zs  + 8*132;            // 4224 B
    float* pAz = ssm + 8*132;            // 512 B
    float* pAs = pAz + 128;              // 512 B   (total 9472 <= 12288)

    const int row = (tid >> 1) + (tid & 1)*64;
    #pragma unroll
    for (int j = 0; j < 8; j++) { zs[j*132 + row] = z[j]; ssm[j*132 + row] = s[j]; }
    __syncthreads();
    {
        const int h = tid >> 6, col = (tid >> 3) & 7, grp = tid & 7;
        float az = 0.f, as = 0.f;
        #pragma unroll
        for (int i = 0; i < 8; i++) {
            const int a = col*132 + h*64 + grp + 8*i;
            az += zs[a]; as += ssm[a];
        }
        pAz[tid] = az; pAs[tid] = as;
    }
    __syncthreads();
    float qacc = 0.f;
    if (tid < 16) {
        const int h = tid >> 3, col = tid & 7;
        float zt = 0.f, st = 0.f;
        #pragma unroll
        for (int g = 0; g < 8; g++) {
            const int a = h*64 + col*8 + g;
            zt += pAz[a]; st += pAs[a];
        }
        const float sn = st / zt;
        g_S[cb*16 + tid] = sn;
        qacc = sn * sn;
    }
    shn[tid] = qacc;
    __syncthreads();
    if (tid == 0) {
        float t = 0.f;
        #pragma unroll
        for (int i = 0; i < 16; i++) t += shn[i];
        n2out[blockIdx.y*gridDim.x + blockIdx.x] = t;
    }
}

// ---------------------------------------------------------------------------
// k_fin: out = f3 * s3. grid 20 x 1024.
// ---------------------------------------------------------------------------
__global__ __launch_bounds__(1024) void k_fin(float* __restrict__ outp)
{
    const int tid = threadIdx.x;
    __shared__ float sh[1024];
    float acc = g_n2c[tid];
    if (tid < NIT - 1024) acc += g_n2c[1024 + tid];
    sh[tid] = acc;
    __syncthreads();
    for (int st = 512; st > 0; st >>= 1) {
        if (tid < st) sh[tid] += sh[tid + st];
        __syncthreads();
    }
    const float n2 = sh[0];
    const float f  = sqrtf(n2) / (1.0f + n2);
    const int i = blockIdx.x*1024 + tid;
    outp[i] = f * g_S[i];
}

// ---------------------------------------------------------------------------
extern "C" void kernel_launch(void* const* d_in, const int* in_sizes, int n_in,
                              void* d_out, int out_size)
{
    const float* x = (const float*)d_in[0];   // [128,1152,8]
    const float* W = (const float*)d_in[1];   // [10,1152,8,16]
    float* out = (float*)d_out;               // 20480 floats
    (void)in_sizes; (void)n_in; (void)out_size;

    float *n2a, *n2b, *n2c;
    cudaGetSymbolAddress((void**)&n2a, g_n2a);
    cudaGetSymbolAddress((void**)&n2b, g_n2b);
    cudaGetSymbolAddress((void**)&n2c, g_n2c);

    k_u  <<<dim3(NRT, Cc), 128>>>(x, W);
    k_s0 <<<dim3(Bb/2, Cc), 256>>>();                   // iter 1 + n2
    k_it <<<dim3(Bb, Cc), 128>>>(n2a,  640, n2b, 0);    // iter 2
    k_it <<<dim3(Bb, Cc), 128>>>(n2b, NIT, n2c, 1);     // iter 3
    k_fin<<<20, 1024>>>(out);                           // final squash
}